// round 1
// baseline (speedup 1.0000x reference)
#include <cuda_runtime.h>
#include <math.h>

#define RES_UP 0.05f
#define RES_DN 0.02f
#define REQ_UP 0.02f
#define REQ_DN 0.02f

#define MAXG 64

__device__ __forceinline__ float wreduce(float v) {
#pragma unroll
    for (int k = 16; k > 0; k >>= 1) v += __shfl_xor_sync(0xffffffffu, v, k);
    return v;
}

// One warp per LP (b,t). All state register-resident. 2 generator slots/lane.
__global__ __launch_bounds__(128) void pdhg_kernel(
    const float* __restrict__ forecast, const float* __restrict__ pminv,
    const float* __restrict__ pmaxv, const float* __restrict__ bv,
    const float* __restrict__ cv, const int* __restrict__ nitp,
    float* __restrict__ out, int G, int B, int T, float tau)
{
    int warp = (blockIdx.x * blockDim.x + threadIdx.x) >> 5;
    int lane = threadIdx.x & 31;
    int NP = B * T;
    if (warp >= NP) return;
    int bb = warp / T;
    int t  = warp - bb * T;
    float D = forecast[warp];
    int nit = *nitp;
    float sig = tau;

    int g0 = lane, g1 = lane + 32;
    bool m0 = g0 < G, m1 = g1 < G;
    float px0 = m0 ? pmaxv[g0] : 0.f, px1 = m1 ? pmaxv[g1] : 0.f;
    float pn0 = m0 ? pminv[g0] : 0.f, pn1 = m1 ? pminv[g1] : 0.f;
    float b0  = m0 ? bv[g0]    : 0.f, b1  = m1 ? bv[g1]    : 0.f;
    float cu0 = RES_UP * b0, cu1 = RES_UP * b1;
    float cd0 = RES_DN * b0, cd1 = RES_DN * b1;

    // primal x = (P, Ru, Rd), dual y = (y0, a, d, u, l, yu, yd)
    float P0 = 0, P1 = 0, Ru0 = 0, Ru1 = 0, Rd0 = 0, Rd1 = 0;
    float a0 = 0, a1 = 0, d0 = 0, d1 = 0, u0 = 0, u1 = 0, l0 = 0, l1 = 0;
    float y0 = 0, yu = 0, yd = 0;

    for (int it = 0; it < nit; ++it) {
        // x_new = max(x - tau*(c_obj + K^T y), 0)
        float Pn0 = fmaxf(P0 - tau * (b0 + y0 + a0 - d0 + u0 - l0), 0.f);
        float Pn1 = fmaxf(P1 - tau * (b1 + y0 + a1 - d1 + u1 - l1), 0.f);
        float Run0 = fmaxf(Ru0 - tau * (cu0 + a0 - yu), 0.f);
        float Run1 = fmaxf(Ru1 - tau * (cu1 + a1 - yu), 0.f);
        float Rdn0 = fmaxf(Rd0 - tau * (cd0 + d0 - yd), 0.f);
        float Rdn1 = fmaxf(Rd1 - tau * (cd1 + d1 - yd), 0.f);
        if (!m1) { Pn1 = 0.f; Run1 = 0.f; Rdn1 = 0.f; }
        // x_bar = 2*x_new - x
        float Pb0 = 2.f * Pn0 - P0,   Pb1 = 2.f * Pn1 - P1;
        float Rub0 = 2.f * Run0 - Ru0, Rub1 = 2.f * Run1 - Ru1;
        float Rdb0 = 2.f * Rdn0 - Rd0, Rdb1 = 2.f * Rdn1 - Rd1;
        P0 = Pn0; P1 = Pn1; Ru0 = Run0; Ru1 = Run1; Rd0 = Rdn0; Rd1 = Rdn1;

        float sP  = wreduce(Pb0 + Pb1);
        float sRu = wreduce(Rub0 + Rub1);
        float sRd = wreduce(Rdb0 + Rdb1);

        // y_new = y + sigma*(K x_bar - q), project inequality rows to >= 0
        y0 = y0 + sig * (sP - D);
        a0 = fmaxf(a0 + sig * (Pb0 + Rub0 - px0), 0.f);
        a1 = fmaxf(a1 + sig * (Pb1 + Rub1 - px1), 0.f);
        d0 = fmaxf(d0 + sig * (Rdb0 - Pb0 + pn0), 0.f);
        d1 = fmaxf(d1 + sig * (Rdb1 - Pb1 + pn1), 0.f);
        u0 = fmaxf(u0 + sig * (Pb0 - px0), 0.f);
        u1 = fmaxf(u1 + sig * (Pb1 - px1), 0.f);
        l0 = fmaxf(l0 + sig * (pn0 - Pb0), 0.f);
        l1 = fmaxf(l1 + sig * (pn1 - Pb1), 0.f);
        yu = fmaxf(yu + sig * (REQ_UP * D - sRu), 0.f);
        yd = fmaxf(yd + sig * (REQ_DN * D - sRd), 0.f);
    }

    // outputs: P_DA | R_up | R_dn | obj | Cost_DA, arrays in (B, G, T)
    size_t BGT = (size_t)B * G * T;
    float* Pout = out;
    float* Ruo  = out + BGT;
    float* Rdo  = out + 2 * BGT;
    float* Co   = out + 3 * BGT + B;
    if (m0) {
        size_t i0 = ((size_t)bb * G + g0) * T + t;
        Pout[i0] = P0; Ruo[i0] = Ru0; Rdo[i0] = Rd0;
        Co[i0] = fmaf(b0, P0, cv[g0]);
    }
    if (m1) {
        size_t i1 = ((size_t)bb * G + g1) * T + t;
        Pout[i1] = P1; Ruo[i1] = Ru1; Rdo[i1] = Rd1;
        Co[i1] = fmaf(b1, P1, cv[g1]);
    }
}

// Deterministic per-batch objective reduction (no atomics).
__global__ __launch_bounds__(128) void obj_kernel(
    const float* __restrict__ out, const float* __restrict__ bv,
    int G, int B, int T)
{
    int bb = blockIdx.x;
    int tid = threadIdx.x;
    size_t BGT = (size_t)B * G * T;
    const float* Ruo = out + BGT;
    const float* Rdo = out + 2 * BGT;
    const float* Co  = out + 3 * BGT + B;
    float* objo = (float*)(out + 3 * BGT);

    int GT = G * T;
    size_t base = (size_t)bb * GT;
    float s = 0.f;
    for (int idx = tid; idx < GT; idx += 128) {
        int g = idx / T;
        float bg = bv[g];
        s += Co[base + idx] + RES_UP * bg * Ruo[base + idx] + RES_DN * bg * Rdo[base + idx];
    }
    __shared__ float sm[128];
    sm[tid] = s;
    __syncthreads();
#pragma unroll
    for (int k = 64; k > 0; k >>= 1) {
        if (tid < k) sm[tid] += sm[tid + k];
        __syncthreads();
    }
    if (tid == 0) objo[bb] = sm[0];
}

// ---------------- host: structured spectral norm of K (power iteration) -----
static void K_matvec(const double* v, double* w, int G) {
    int n1 = G, n2 = 2 * G;
    double s0 = 0, s1 = 0, s2 = 0;
    for (int g = 0; g < G; ++g) { s0 += v[g]; s1 += v[n1 + g]; s2 += v[n2 + g]; }
    w[0] = s0;
    for (int g = 0; g < G; ++g) {
        w[1 + g]          =  v[g] + v[n1 + g];
        w[1 + G + g]      = -v[g] + v[n2 + g];
        w[1 + 2 * G + g]  =  v[g];
        w[1 + 3 * G + g]  = -v[g];
    }
    w[1 + 4 * G]     = -s1;
    w[1 + 4 * G + 1] = -s2;
}

static void KT_matvec(const double* w, double* z, int G) {
    double yu = w[1 + 4 * G], yd = w[1 + 4 * G + 1];
    for (int g = 0; g < G; ++g) {
        z[g]           = w[0] + w[1 + g] - w[1 + G + g] + w[1 + 2 * G + g] - w[1 + 3 * G + g];
        z[G + g]       = w[1 + g] - yu;
        z[2 * G + g]   = w[1 + G + g] - yd;
    }
}

static double spectral_norm_K(int G) {
    static double v[3 * MAXG], w[4 * MAXG + 3], z[3 * MAXG];
    int n = 3 * G;
    for (int i = 0; i < n; ++i) v[i] = 1.0 + 0.001 * (double)(i % 7);
    double lam = 1.0;
    for (int it = 0; it < 4000; ++it) {
        K_matvec(v, w, G);
        KT_matvec(w, z, G);
        double nrm = 0.0;
        for (int i = 0; i < n; ++i) nrm += z[i] * z[i];
        nrm = sqrt(nrm);
        lam = nrm;
        double inv = 1.0 / nrm;
        for (int i = 0; i < n; ++i) v[i] = z[i] * inv;
    }
    return sqrt(lam);  // sigma_max(K)
}

extern "C" void kernel_launch(void* const* d_in, const int* in_sizes, int n_in,
                              void* d_out, int out_size) {
    const float* forecast = (const float*)d_in[0];
    const float* pminv    = (const float*)d_in[1];
    const float* pmaxv    = (const float*)d_in[2];
    const float* bv       = (const float*)d_in[3];
    const float* cv       = (const float*)d_in[4];
    const int*   nitp     = (const int*)d_in[5];

    int G  = in_sizes[1];
    int BT = in_sizes[0];
    // out_size = 4*B*G*T + B  with  B*T = BT  ->  B = out_size - 4*G*BT
    int B = out_size - 4 * G * BT;
    if (B <= 0) B = 1;
    int T = BT / B;

    double L = spectral_norm_K(G);
    float tau = (float)(0.9 / L);

    float* out = (float*)d_out;
    int warpsPerBlock = 4;
    int blocks = (BT + warpsPerBlock - 1) / warpsPerBlock;
    pdhg_kernel<<<blocks, warpsPerBlock * 32>>>(
        forecast, pminv, pmaxv, bv, cv, nitp, out, G, B, T, tau);
    obj_kernel<<<B, 128>>>(out, bv, G, B, T);
}

// round 3
// speedup vs baseline: 1.5358x; 1.5358x over previous
#include <cuda_runtime.h>
#include <math.h>

#define RES_UP 0.05f
#define RES_DN 0.02f
#define REQ_UP 0.02f
#define REQ_DN 0.02f

#define MAXG 64

typedef unsigned long long u64;

// per-LP objective partials (B*T <= 8192)
__device__ float g_partial[8192];

// ---------- packed f32x2 helpers (sm_100+) ----------
__device__ __forceinline__ u64 pk(float lo, float hi) {
    u64 r; asm("mov.b64 %0, {%1,%2};" : "=l"(r) : "f"(lo), "f"(hi)); return r;
}
__device__ __forceinline__ void upk(u64 p, float& lo, float& hi) {
    asm("mov.b64 {%0,%1}, %2;" : "=f"(lo), "=f"(hi) : "l"(p));
}
__device__ __forceinline__ u64 f2add(u64 a, u64 b) {
    u64 r; asm("add.rn.f32x2 %0, %1, %2;" : "=l"(r) : "l"(a), "l"(b)); return r;
}
__device__ __forceinline__ u64 f2fma(u64 a, u64 b, u64 c) {
    u64 r; asm("fma.rn.f32x2 %0, %1, %2, %3;" : "=l"(r) : "l"(a), "l"(b), "l"(c)); return r;
}
__device__ __forceinline__ u64 f2sub(u64 a, u64 b) {
    const u64 N1 = 0xBF800000BF800000ULL;  // (-1.0f, -1.0f)
    return f2fma(b, N1, a);                // a - b (exact)
}
__device__ __forceinline__ u64 f2relu(u64 a) {
    float lo, hi; upk(a, lo, hi);
    return pk(fmaxf(lo, 0.f), fmaxf(hi, 0.f));
}

// One 16-lane group per LP; 2 LPs per warp; 4 gen slots/lane = 2 packed pairs.
// Slot s, group-lane l -> gen g = s*16 + l. Pair p holds slots (2p, 2p+1):
// lo gen = 32p + l, hi gen = 32p + 16 + l. Dead gens (g>=G) use poisoned
// constants (b=1e30, pmax=pmin=0) which keep their state at exactly 0.
__global__ __launch_bounds__(32) void pdhg_kernel(
    const float* __restrict__ forecast, const float* __restrict__ pminv,
    const float* __restrict__ pmaxv, const float* __restrict__ bv,
    const float* __restrict__ cv, const int* __restrict__ nitp,
    float* __restrict__ out, int G, int B, int T, float tau)
{
    const int lane = threadIdx.x;
    const int grp  = lane >> 4;
    const int gl   = lane & 15;
    const int NP   = B * T;
    const int lp   = blockIdx.x * 2 + grp;
    const bool live = lp < NP;
    const int lpc  = live ? lp : NP - 1;
    const float D  = forecast[lpc];
    const int nit  = *nitp;
    const float sig = tau;

    u64 tb[2], tcu[2], tcd[2], spx[2], spn[2];
#pragma unroll
    for (int p = 0; p < 2; ++p) {
        int glo = 32 * p + gl, ghi = glo + 16;
        float blo  = (glo < G) ? bv[glo]    : 1e30f;
        float bhi  = (ghi < G) ? bv[ghi]    : 1e30f;
        float pxlo = (glo < G) ? pmaxv[glo] : 0.f;
        float pxhi = (ghi < G) ? pmaxv[ghi] : 0.f;
        float pnlo = (glo < G) ? pminv[glo] : 0.f;
        float pnhi = (ghi < G) ? pminv[ghi] : 0.f;
        tb[p]  = pk(tau * blo,          tau * bhi);
        tcu[p] = pk(tau * RES_UP * blo, tau * RES_UP * bhi);
        tcd[p] = pk(tau * RES_DN * blo, tau * RES_DN * bhi);
        spx[p] = pk(sig * pxlo,         sig * pxhi);
        spn[p] = pk(sig * pnlo,         sig * pnhi);
    }
    const u64 NTAU = pk(-tau, -tau);
    const u64 SIGp = pk(sig, sig);
    const u64 NSIG = pk(-sig, -sig);
    const float ruD = REQ_UP * D, rdD = REQ_DN * D;

    // packed state: primal (P, Ru, Rd), per-gen duals (a, d, u, l)
    u64 P[2]  = {0, 0}, Ru[2] = {0, 0}, Rd[2] = {0, 0};
    u64 av[2] = {0, 0}, dv[2] = {0, 0}, uv[2] = {0, 0}, lv[2] = {0, 0};
    float y0 = 0.f, yu = 0.f, yd = 0.f;

    for (int it = 0; it < nit; ++it) {
        u64 ty0p = pk(tau * y0, tau * y0);
        u64 tyup = pk(tau * yu, tau * yu);
        u64 tydp = pk(tau * yd, tau * yd);
        u64 Pb[2], Rub[2], Rdb[2];
#pragma unroll
        for (int p = 0; p < 2; ++p) {
            // x_new = relu(x - tau*(c_obj + K^T y))
            u64 t1 = f2sub(av[p], dv[p]);
            u64 t2 = f2sub(uv[p], lv[p]);
            u64 t3 = f2add(t1, t2);
            u64 e  = f2sub(P[p], tb[p]);
            e = f2sub(e, ty0p);
            e = f2fma(NTAU, t3, e);
            u64 Pn = f2relu(e);

            e = f2sub(Ru[p], tcu[p]);
            e = f2fma(NTAU, av[p], e);
            e = f2add(e, tyup);
            u64 Run = f2relu(e);

            e = f2sub(Rd[p], tcd[p]);
            e = f2fma(NTAU, dv[p], e);
            e = f2add(e, tydp);
            u64 Rdn = f2relu(e);

            // x_bar = 2*x_new - x_old
            Pb[p]  = f2sub(f2add(Pn, Pn),   P[p]);
            Rub[p] = f2sub(f2add(Run, Run), Ru[p]);
            Rdb[p] = f2sub(f2add(Rdn, Rdn), Rd[p]);
            P[p] = Pn; Ru[p] = Run; Rd[p] = Rdn;

            // per-gen dual updates (use x_bar, old scalar duals unaffected)
            u64 t = f2add(Pb[p], Rub[p]);
            av[p] = f2relu(f2fma(SIGp, t, f2sub(av[p], spx[p])));
            t = f2sub(Rdb[p], Pb[p]);
            dv[p] = f2relu(f2fma(SIGp, t, f2add(dv[p], spn[p])));
            uv[p] = f2relu(f2fma(SIGp, Pb[p], f2sub(uv[p], spx[p])));
            lv[p] = f2relu(f2fma(NSIG, Pb[p], f2add(lv[p], spn[p])));
        }
        // group-wide sums of x_bar components (16-lane butterfly)
        float sP, sRu, sRd;
        { u64 s = f2add(Pb[0],  Pb[1]);  float x, y; upk(s, x, y); sP  = x + y; }
        { u64 s = f2add(Rub[0], Rub[1]); float x, y; upk(s, x, y); sRu = x + y; }
        { u64 s = f2add(Rdb[0], Rdb[1]); float x, y; upk(s, x, y); sRd = x + y; }
#pragma unroll
        for (int k = 8; k > 0; k >>= 1) {
            sP  += __shfl_xor_sync(0xffffffffu, sP,  k);
            sRu += __shfl_xor_sync(0xffffffffu, sRu, k);
            sRd += __shfl_xor_sync(0xffffffffu, sRd, k);
        }
        // scalar dual rows
        y0 = fmaf(sig, sP - D, y0);
        yu = fmaxf(fmaf(sig, ruD - sRu, yu), 0.f);
        yd = fmaxf(fmaf(sig, rdD - sRd, yd), 0.f);
    }

    // outputs: P_DA | R_up | R_dn | obj | Cost_DA, all (B, G, T)
    size_t BGT = (size_t)B * G * T;
    float* Pout = out;
    float* Ruo  = out + BGT;
    float* Rdo  = out + 2 * BGT;
    float* Co   = out + 3 * BGT + B;
    const int bb = lpc / T, t = lpc - bb * T;

    float part = 0.f;
    if (live) {
#pragma unroll
        for (int p = 0; p < 2; ++p) {
            float Plo, Phi, Rulo, Ruhi, Rdlo, Rdhi;
            upk(P[p], Plo, Phi);
            upk(Ru[p], Rulo, Ruhi);
            upk(Rd[p], Rdlo, Rdhi);
            int glo = 32 * p + gl, ghi = glo + 16;
            if (glo < G) {
                size_t i = ((size_t)bb * G + glo) * T + t;
                float bg = bv[glo];
                float co = fmaf(bg, Plo, cv[glo]);
                Pout[i] = Plo; Ruo[i] = Rulo; Rdo[i] = Rdlo; Co[i] = co;
                part += co + RES_UP * bg * Rulo + RES_DN * bg * Rdlo;
            }
            if (ghi < G) {
                size_t i = ((size_t)bb * G + ghi) * T + t;
                float bg = bv[ghi];
                float co = fmaf(bg, Phi, cv[ghi]);
                Pout[i] = Phi; Ruo[i] = Ruhi; Rdo[i] = Rdhi; Co[i] = co;
                part += co + RES_UP * bg * Ruhi + RES_DN * bg * Rdhi;
            }
        }
    }
#pragma unroll
    for (int k = 8; k > 0; k >>= 1)
        part += __shfl_xor_sync(0xffffffffu, part, k);
    if (live && gl == 0) g_partial[lp] = part;
}

// Sum T per-LP partials -> obj[b]. One warp per batch element.
__global__ __launch_bounds__(32) void obj_kernel(
    float* __restrict__ out, int G, int B, int T)
{
    int bb = blockIdx.x;
    int lane = threadIdx.x;
    size_t BGT = (size_t)B * G * T;
    float v = (lane < T) ? g_partial[bb * T + lane] : 0.f;
#pragma unroll
    for (int k = 16; k > 0; k >>= 1)
        v += __shfl_xor_sync(0xffffffffu, v, k);
    if (lane == 0) out[3 * BGT + bb] = v;
}

// ---------------- host: structured spectral norm of K (power iteration) -----
static void K_matvec(const double* v, double* w, int G) {
    int n1 = G, n2 = 2 * G;
    double s0 = 0, s1 = 0, s2 = 0;
    for (int g = 0; g < G; ++g) { s0 += v[g]; s1 += v[n1 + g]; s2 += v[n2 + g]; }
    w[0] = s0;
    for (int g = 0; g < G; ++g) {
        w[1 + g]          =  v[g] + v[n1 + g];
        w[1 + G + g]      = -v[g] + v[n2 + g];
        w[1 + 2 * G + g]  =  v[g];
        w[1 + 3 * G + g]  = -v[g];
    }
    w[1 + 4 * G]     = -s1;
    w[1 + 4 * G + 1] = -s2;
}

static void KT_matvec(const double* w, double* z, int G) {
    double yu = w[1 + 4 * G], yd = w[1 + 4 * G + 1];
    for (int g = 0; g < G; ++g) {
        z[g]           = w[0] + w[1 + g] - w[1 + G + g] + w[1 + 2 * G + g] - w[1 + 3 * G + g];
        z[G + g]       = w[1 + g] - yu;
        z[2 * G + g]   = w[1 + G + g] - yd;
    }
}

static double spectral_norm_K(int G) {
    static double v[3 * MAXG], w[4 * MAXG + 3], z[3 * MAXG];
    int n = 3 * G;
    for (int i = 0; i < n; ++i) v[i] = 1.0 + 0.001 * (double)(i % 7);
    double lam = 1.0;
    for (int it = 0; it < 4000; ++it) {
        K_matvec(v, w, G);
        KT_matvec(w, z, G);
        double nrm = 0.0;
        for (int i = 0; i < n; ++i) nrm += z[i] * z[i];
        nrm = sqrt(nrm);
        lam = nrm;
        double inv = 1.0 / nrm;
        for (int i = 0; i < n; ++i) v[i] = z[i] * inv;
    }
    return sqrt(lam);  // sigma_max(K)
}

extern "C" void kernel_launch(void* const* d_in, const int* in_sizes, int n_in,
                              void* d_out, int out_size) {
    const float* forecast = (const float*)d_in[0];
    const float* pminv    = (const float*)d_in[1];
    const float* pmaxv    = (const float*)d_in[2];
    const float* bv       = (const float*)d_in[3];
    const float* cv       = (const float*)d_in[4];
    const int*   nitp     = (const int*)d_in[5];

    int G  = in_sizes[1];
    int BT = in_sizes[0];
    // out_size = 4*B*G*T + B  with  B*T = BT  ->  B = out_size - 4*G*BT
    int B = out_size - 4 * G * BT;
    if (B <= 0) B = 1;
    int T = BT / B;

    double L = spectral_norm_K(G);
    float tau = (float)(0.9 / L);

    float* out = (float*)d_out;
    int blocks = (BT + 1) / 2;  // 2 LPs per 32-thread block (one warp)
    pdhg_kernel<<<blocks, 32>>>(
        forecast, pminv, pmaxv, bv, cv, nitp, out, G, B, T, tau);
    obj_kernel<<<B, 32>>>(out, G, B, T);
}